// round 4
// baseline (speedup 1.0000x reference)
#include <cuda_runtime.h>
#include <cuda_bf16.h>
#include <cstdint>

// SINSentAddEmb: out[b,n,:] = LayerNorm(pe[n] + pe[para[b,n]] + pe[sent[b,n]]) * gamma + beta
// top_vecs (d_in[0]) is unused by the reference math — never read it (saves 134 MB HBM).
//
// R2 restructure (re-bench after infra failure): 128 threads cooperate on one row
// (was: 1 warp/row). Cuts per-thread register footprint (2 float4 row chunks instead
// of 8; 6 in-flight loads instead of 24) to lift occupancy from 32% -> ~65% and hide
// DRAM gather latency.
//
// Fixed shape: B=8, N=4096, H=1024, MAX_NSENT=5000, EPS=1e-12.
// sent_struct_vec is int32 on device (JAX downcasts int64 with x64 off).

#define HDIM    1024
#define H4      (HDIM / 4)     // 256 float4 per row
#define NPOS    4096           // sequence length (power of two)
#define TPR     128            // threads per row
#define ROWS_PB 2              // rows per block -> 256-thread blocks
#define EPS_LN  1e-12f

__global__ __launch_bounds__(TPR * ROWS_PB)
void sinsent_addemb_ln_kernel(const int2*   __restrict__ ssv2,    // (B*N) int32 pairs (para, sent)
                              const float4* __restrict__ pe4,     // (MAX_NSENT, H/4)
                              const float4* __restrict__ gamma4,  // (H/4)
                              const float4* __restrict__ beta4,   // (H/4)
                              float4*       __restrict__ out4,    // (B*N, H/4)
                              int rows)
{
    __shared__ float2 part[ROWS_PB][4];       // (sum, sumsq) per warp-group

    const int row_in_blk = threadIdx.x / TPR; // 0..ROWS_PB-1
    const int t          = threadIdx.x & (TPR - 1);
    const int wg         = t >> 5;            // warp index within row group (0..3)
    const int lane       = t & 31;
    const int row        = blockIdx.x * ROWS_PB + row_in_blk;
    if (row >= rows) return;

    const int n = row & (NPOS - 1);           // position within sequence

    // Two int32 indices in one 8B load; uniform across the row group -> broadcast.
    const int2 idx = ssv2[row];

    const float4* __restrict__ pn = pe4 + (size_t)n     * H4;
    const float4* __restrict__ pp = pe4 + (size_t)idx.x * H4;
    const float4* __restrict__ ps = pe4 + (size_t)idx.y * H4;

    const int j0 = t;                         // coalesced across the 128-thread group
    const int j1 = t + TPR;

    // 6 independent LDG.128 -> high MLP, small register footprint.
    const float4 a0 = pn[j0], b0 = pp[j0], c0 = ps[j0];
    const float4 a1 = pn[j1], b1 = pp[j1], c1 = ps[j1];

    float4 e0, e1;
    e0.x = a0.x + b0.x + c0.x;  e0.y = a0.y + b0.y + c0.y;
    e0.z = a0.z + b0.z + c0.z;  e0.w = a0.w + b0.w + c0.w;
    e1.x = a1.x + b1.x + c1.x;  e1.y = a1.y + b1.y + c1.y;
    e1.z = a1.z + b1.z + c1.z;  e1.w = a1.w + b1.w + c1.w;

    float s  = e0.x + e0.y + e0.z + e0.w + e1.x + e1.y + e1.z + e1.w;
    float sq = e0.x * e0.x + e0.y * e0.y + e0.z * e0.z + e0.w * e0.w
             + e1.x * e1.x + e1.y * e1.y + e1.z * e1.z + e1.w * e1.w;

    // Warp butterfly, then combine the 4 warp partials through shared memory.
#pragma unroll
    for (int o = 16; o > 0; o >>= 1) {
        s  += __shfl_xor_sync(0xffffffffu, s,  o);
        sq += __shfl_xor_sync(0xffffffffu, sq, o);
    }
    if (lane == 0) part[row_in_blk][wg] = make_float2(s, sq);
    __syncthreads();

    const float2 p0 = part[row_in_blk][0];
    const float2 p1 = part[row_in_blk][1];
    const float2 p2 = part[row_in_blk][2];
    const float2 p3 = part[row_in_blk][3];
    const float S  = p0.x + p1.x + p2.x + p3.x;
    const float SQ = p0.y + p1.y + p2.y + p3.y;

    const float mean = S  * (1.0f / HDIM);
    const float var  = SQ * (1.0f / HDIM) - mean * mean;
    const float rstd = rsqrtf(var + EPS_LN);

    const float4 g0 = gamma4[j0], t0 = beta4[j0];   // L1/L2-resident (8 KB total)
    const float4 g1 = gamma4[j1], t1 = beta4[j1];

    float4* __restrict__ orow = out4 + (size_t)row * H4;
    float4 o0, o1;
    o0.x = (e0.x - mean) * rstd * g0.x + t0.x;
    o0.y = (e0.y - mean) * rstd * g0.y + t0.y;
    o0.z = (e0.z - mean) * rstd * g0.z + t0.z;
    o0.w = (e0.w - mean) * rstd * g0.w + t0.w;
    o1.x = (e1.x - mean) * rstd * g1.x + t1.x;
    o1.y = (e1.y - mean) * rstd * g1.y + t1.y;
    o1.z = (e1.z - mean) * rstd * g1.z + t1.z;
    o1.w = (e1.w - mean) * rstd * g1.w + t1.w;
    orow[j0] = o0;                            // STG.128, fully coalesced
    orow[j1] = o1;
}

extern "C" void kernel_launch(void* const* d_in, const int* in_sizes, int n_in,
                              void* d_out, int out_size)
{
    // metadata order: [0] top_vecs f32 (UNUSED), [1] sent_struct_vec int32,
    //                 [2] pe f32, [3] gamma f32, [4] beta f32
    const int2*   ssv2   = (const int2*)d_in[1];
    const float4* pe4    = (const float4*)d_in[2];
    const float4* gamma4 = (const float4*)d_in[3];
    const float4* beta4  = (const float4*)d_in[4];
    float4*       out4   = (float4*)d_out;

    const int rows = in_sizes[1] / 2;         // B*N = 32768

    const int threads = TPR * ROWS_PB;        // 256
    const int blocks  = (rows + ROWS_PB - 1) / ROWS_PB;
    sinsent_addemb_ln_kernel<<<blocks, threads>>>(ssv2, pe4, gamma4, beta4, out4, rows);
}

// round 5
// speedup vs baseline: 1.0827x; 1.0827x over previous
#include <cuda_runtime.h>
#include <cuda_bf16.h>
#include <cstdint>

// SINSentAddEmb: out[b,n,:] = LayerNorm(pe[n] + pe[para[b,n]] + pe[sent[b,n]]) * gamma + beta
// top_vecs (d_in[0]) is unused by the reference math — never read it.
//
// R4 restructure: kernel is LTS(L2)-bound (~527 MB through L2 at the ~12 TB/s cap).
// One block per sequence position n; its 8 warps handle the 8 batches. pe[n] is
// staged in shared once per block (4 KB), cutting its L2 traffic 8x (131 -> 16 MB).
// Warps are otherwise fully independent (single barrier per block, R1-style overlap).
//
// Fixed shape: B=8, N=4096, H=1024, MAX_NSENT=5000, EPS=1e-12.
// sent_struct_vec is int32 on device (JAX downcasts int64 with x64 off).

#define HDIM   1024
#define H4     (HDIM / 4)      // 256 float4 per row
#define NPOS   4096            // sequence length
#define NBATCH 8
#define EPS_LN 1e-12f

__global__ __launch_bounds__(NBATCH * 32)
void sinsent_addemb_ln_kernel(const int2*   __restrict__ ssv2,    // (B*N) int32 pairs (para, sent)
                              const float4* __restrict__ pe4,     // (MAX_NSENT, H/4)
                              const float4* __restrict__ gamma4,  // (H/4)
                              const float4* __restrict__ beta4,   // (H/4)
                              float4*       __restrict__ out4)    // (B*N, H/4)
{
    __shared__ float4 spe[H4];                // pe[n] staged once per block (4 KB)

    const int n    = blockIdx.x;              // sequence position
    const int b    = threadIdx.x >> 5;        // warp = batch index
    const int lane = threadIdx.x & 31;

    // Stage pe[n]: 256 threads x 1 float4 = 4 KB, one coalesced L2 read per block.
    spe[threadIdx.x] = pe4[(size_t)n * H4 + threadIdx.x];
    __syncthreads();                          // only barrier; warps independent after this

    const int row = b * NPOS + n;             // output row (b, n)
    const int2 idx = ssv2[row];               // uniform in warp -> broadcast

    const float4* __restrict__ pp = pe4 + (size_t)idx.x * H4;
    const float4* __restrict__ ps = pe4 + (size_t)idx.y * H4;

    // Gather + sum: 8 float4 per lane, held in registers. 16 independent LDG.128
    // front-batched for MLP; pe[n] comes from shared.
    float4 e[8];
    float s = 0.0f, sq = 0.0f;
#pragma unroll
    for (int i = 0; i < 8; i++) {
        const int j = i * 32 + lane;          // coalesced: 32 lanes x 16B = 512B per stream
        const float4 a = spe[j];
        const float4 bb = pp[j];
        const float4 c = ps[j];
        float4 v;
        v.x = a.x + bb.x + c.x;
        v.y = a.y + bb.y + c.y;
        v.z = a.z + bb.z + c.z;
        v.w = a.w + bb.w + c.w;
        e[i] = v;
        s  += v.x + v.y + v.z + v.w;
        sq += v.x * v.x + v.y * v.y + v.z * v.z + v.w * v.w;
    }

    // Warp-wide butterfly reduction of (sum, sumsq) — no cross-warp coupling.
#pragma unroll
    for (int o = 16; o > 0; o >>= 1) {
        s  += __shfl_xor_sync(0xffffffffu, s,  o);
        sq += __shfl_xor_sync(0xffffffffu, sq, o);
    }

    const float mean = s  * (1.0f / HDIM);
    const float var  = sq * (1.0f / HDIM) - mean * mean;
    const float rstd = rsqrtf(var + EPS_LN);

    float4* __restrict__ orow = out4 + (size_t)row * H4;
#pragma unroll
    for (int i = 0; i < 8; i++) {
        const int j = i * 32 + lane;
        const float4 g  = gamma4[j];          // L1-resident after first touch (8 KB total)
        const float4 bt = beta4[j];
        const float4 v  = e[i];
        float4 o;
        o.x = (v.x - mean) * rstd * g.x + bt.x;
        o.y = (v.y - mean) * rstd * g.y + bt.y;
        o.z = (v.z - mean) * rstd * g.z + bt.z;
        o.w = (v.w - mean) * rstd * g.w + bt.w;
        orow[j] = o;                          // STG.128, fully coalesced
    }
}

extern "C" void kernel_launch(void* const* d_in, const int* in_sizes, int n_in,
                              void* d_out, int out_size)
{
    // metadata order: [0] top_vecs f32 (UNUSED), [1] sent_struct_vec int32,
    //                 [2] pe f32, [3] gamma f32, [4] beta f32
    const int2*   ssv2   = (const int2*)d_in[1];
    const float4* pe4    = (const float4*)d_in[2];
    const float4* gamma4 = (const float4*)d_in[3];
    const float4* beta4  = (const float4*)d_in[4];
    float4*       out4   = (float4*)d_out;

    sinsent_addemb_ln_kernel<<<NPOS, NBATCH * 32>>>(ssv2, pe4, gamma4, beta4, out4);
}